// round 1
// baseline (speedup 1.0000x reference)
#include <cuda_runtime.h>

#ifndef BATCH_THREADS
#define BATCH_THREADS 256
#endif

// 3x3 matmul: out = a * b (row-major 3x3 in flat [9])
__device__ __forceinline__ void mm3(float* __restrict__ o,
                                    const float* __restrict__ a,
                                    const float* __restrict__ b) {
#pragma unroll
    for (int i = 0; i < 3; i++) {
#pragma unroll
        for (int j = 0; j < 3; j++) {
            float s = a[3 * i + 0] * b[0 + j];
            s = fmaf(a[3 * i + 1], b[3 + j], s);
            s = fmaf(a[3 * i + 2], b[6 + j], s);
            o[3 * i + j] = s;
        }
    }
}

__global__ void __launch_bounds__(BATCH_THREADS)
transop_expm_kernel(const float* __restrict__ c,
                    const float* __restrict__ x,
                    const float* __restrict__ psi,
                    float* __restrict__ out,
                    int B) {
    // Stage the 54 psi floats in shared memory (uniform broadcast reads later).
    __shared__ float sp[54];
    if (threadIdx.x < 54) sp[threadIdx.x] = psi[threadIdx.x];
    __syncthreads();

    int b = blockIdx.x * BATCH_THREADS + threadIdx.x;
    if (b >= B) return;

    // Load c[b, 0..5] as three float2 (24B per thread, contiguous across warp).
    const float2* c2 = reinterpret_cast<const float2*>(c);
    float2 ca = c2[3 * b + 0];
    float2 cb = c2[3 * b + 1];
    float2 cd = c2[3 * b + 2];
    float cc[6] = {ca.x, ca.y, cb.x, cb.y, cd.x, cd.y};

    // T = sum_m cc[m] * psi[m]   (9 entries)
    float T[9];
#pragma unroll
    for (int p = 0; p < 9; p++) {
        float t = cc[0] * sp[p];
#pragma unroll
        for (int m = 1; m < 6; m++) t = fmaf(cc[m], sp[m * 9 + p], t);
        T[p] = t;
    }

    // inf-norm (max abs row sum)
    float r0 = fabsf(T[0]) + fabsf(T[1]) + fabsf(T[2]);
    float r1 = fabsf(T[3]) + fabsf(T[4]) + fabsf(T[5]);
    float r2 = fabsf(T[6]) + fabsf(T[7]) + fabsf(T[8]);
    float a = fmaxf(r0, fmaxf(r1, r2));

    // s = ceil(log2(a / theta)), theta = 0.25; exact power-of-two scale 2^-s.
    const float inv_theta = 4.0f;  // 1/0.25
    float ratio = a * inv_theta;
    int s = 0;
    if (ratio > 1.0f) {
        // exponent of ratio: ratio in [2^e, 2^{e+1}) -> s = e + 1
        int bits = __float_as_int(ratio);
        int e = ((bits >> 23) & 0xFF) - 127;
        s = e + 1;
        if (s > 30) s = 30;  // paranoia clamp (never hit for sane inputs)
    }
    float sc = __int_as_float((127 - s) << 23);  // 2^-s

#pragma unroll
    for (int p = 0; p < 9; p++) T[p] *= sc;

    // Order-5 Taylor: E = I + T + T^2/2 + T^3/6 + T^2*(T^2/24 + T^3/120)
    float T2[9], T3[9], W[9], Q[9], E[9];
    mm3(T2, T, T);
    mm3(T3, T2, T);
#pragma unroll
    for (int p = 0; p < 9; p++)
        W[p] = fmaf(T3[p], (1.0f / 120.0f), T2[p] * (1.0f / 24.0f));
    mm3(Q, T2, W);
#pragma unroll
    for (int p = 0; p < 9; p++) {
        float e0 = (p == 0 || p == 4 || p == 8) ? 1.0f : 0.0f;
        e0 += T[p];
        e0 = fmaf(T2[p], 0.5f, e0);
        e0 = fmaf(T3[p], (1.0f / 6.0f), e0);
        E[p] = e0 + Q[p];
    }

    // s squarings
    for (int i = 0; i < s; i++) {
        float Tmp[9];
        mm3(Tmp, E, E);
#pragma unroll
        for (int p = 0; p < 9; p++) E[p] = Tmp[p];
    }

    // y = E * x[b]
    float x0 = x[3 * b + 0];
    float x1 = x[3 * b + 1];
    float x2 = x[3 * b + 2];

    float y0 = fmaf(E[0], x0, fmaf(E[1], x1, E[2] * x2));
    float y1 = fmaf(E[3], x0, fmaf(E[4], x1, E[5] * x2));
    float y2 = fmaf(E[6], x0, fmaf(E[7], x1, E[8] * x2));

    out[3 * b + 0] = y0;
    out[3 * b + 1] = y1;
    out[3 * b + 2] = y2;
}

extern "C" void kernel_launch(void* const* d_in, const int* in_sizes, int n_in,
                              void* d_out, int out_size) {
    // Identify inputs by element count (robust to metadata ordering):
    //   psi : 54 elements (M*N*N = 6*3*3)
    //   c   : B*6
    //   x   : B*3
    const float* c = nullptr;
    const float* x = nullptr;
    const float* psi = nullptr;
    long long maxsz = 0;
    for (int i = 0; i < n_in; i++)
        if ((long long)in_sizes[i] > maxsz) maxsz = in_sizes[i];
    // maxsz = B*6 -> B
    int B = (int)(maxsz / 6);
    for (int i = 0; i < n_in; i++) {
        if (in_sizes[i] == 54) psi = (const float*)d_in[i];
        else if (in_sizes[i] == B * 6) c = (const float*)d_in[i];
        else if (in_sizes[i] == B * 3) x = (const float*)d_in[i];
    }

    float* out = (float*)d_out;
    int grid = (B + BATCH_THREADS - 1) / BATCH_THREADS;
    transop_expm_kernel<<<grid, BATCH_THREADS>>>(c, x, psi, out, B);
}

// round 2
// speedup vs baseline: 1.0846x; 1.0846x over previous
#include <cuda_runtime.h>

#ifndef BATCH_THREADS
#define BATCH_THREADS 256
#endif

// ---------- packed f32x2 helpers (FFMA2 path, PTX-only) ----------
typedef unsigned long long u64;

__device__ __forceinline__ u64 pk(float lo, float hi) {
    u64 r;
    asm("mov.b64 %0, {%1, %2};" : "=l"(r) : "f"(lo), "f"(hi));
    return r;
}
__device__ __forceinline__ void upk(float& lo, float& hi, u64 v) {
    asm("mov.b64 {%0, %1}, %2;" : "=f"(lo), "=f"(hi) : "l"(v));
}
__device__ __forceinline__ u64 f2fma(u64 a, u64 b, u64 c) {
    u64 d;
    asm("fma.rn.f32x2 %0, %1, %2, %3;" : "=l"(d) : "l"(a), "l"(b), "l"(c));
    return d;
}
__device__ __forceinline__ u64 f2mul(u64 a, u64 b) {
    u64 d;
    asm("mul.rn.f32x2 %0, %1, %2;" : "=l"(d) : "l"(a), "l"(b));
    return d;
}
__device__ __forceinline__ u64 f2add(u64 a, u64 b) {
    u64 d;
    asm("add.rn.f32x2 %0, %1, %2;" : "=l"(d) : "l"(a), "l"(b));
    return d;
}
__device__ __forceinline__ u64 f2abs(u64 a) { return a & 0x7FFFFFFF7FFFFFFFull; }

// packed 3x3 matmul: o = a * b  (flat row-major [9], each entry = f32x2)
__device__ __forceinline__ void mm3p(u64* __restrict__ o,
                                     const u64* __restrict__ a,
                                     const u64* __restrict__ b) {
#pragma unroll
    for (int i = 0; i < 3; i++) {
#pragma unroll
        for (int j = 0; j < 3; j++) {
            u64 s = f2mul(a[3 * i + 0], b[0 + j]);
            s = f2fma(a[3 * i + 1], b[3 + j], s);
            s = f2fma(a[3 * i + 2], b[6 + j], s);
            o[3 * i + j] = s;
        }
    }
}

__global__ void __launch_bounds__(BATCH_THREADS)
transop_expm_kernel(const float* __restrict__ c,
                    const float* __restrict__ x,
                    const float* __restrict__ psi,
                    float* __restrict__ out,
                    int B) {
    // psi broadcast into shared as packed (v, v) pairs -> LDS.64 broadcasts later
    __shared__ u64 sp2[54];
    if (threadIdx.x < 54) {
        float v = psi[threadIdx.x];
        sp2[threadIdx.x] = pk(v, v);
    }
    __syncthreads();

    int t = blockIdx.x * BATCH_THREADS + threadIdx.x;  // thread handles items 2t, 2t+1
    int b0 = 2 * t;
    if (b0 + 1 >= B + 1) return;  // B is even; guard anyway
    if (b0 >= B) return;

    // ---- load c for both items: 12 contiguous floats = 3x float4 ----
    const float4* c4 = reinterpret_cast<const float4*>(c);
    float4 A  = c4[3 * t + 0];  // c0[0..3]
    float4 Bv = c4[3 * t + 1];  // c0[4], c0[5], c1[0], c1[1]
    float4 Cv = c4[3 * t + 2];  // c1[2..5]
    u64 cc[6];
    cc[0] = pk(A.x,  Bv.z);
    cc[1] = pk(A.y,  Bv.w);
    cc[2] = pk(A.z,  Cv.x);
    cc[3] = pk(A.w,  Cv.y);
    cc[4] = pk(Bv.x, Cv.z);
    cc[5] = pk(Bv.y, Cv.w);

    // ---- load x for both items: 6 contiguous floats = 3x float2 ----
    const float2* x2 = reinterpret_cast<const float2*>(x);
    float2 X0 = x2[3 * t + 0];  // x0_0, x0_1
    float2 X1 = x2[3 * t + 1];  // x0_2, x1_0
    float2 X2 = x2[3 * t + 2];  // x1_1, x1_2
    u64 xv0 = pk(X0.x, X1.y);
    u64 xv1 = pk(X0.y, X2.x);
    u64 xv2 = pk(X1.x, X2.y);

    // ---- T = sum_m cc[m] * psi[m] (packed over 2 items) ----
    u64 T[9];
#pragma unroll
    for (int p = 0; p < 9; p++) {
        u64 s = f2mul(cc[0], sp2[p]);
#pragma unroll
        for (int m = 1; m < 6; m++) s = f2fma(cc[m], sp2[m * 9 + p], s);
        T[p] = s;
    }

    // ---- inf-norm across both lanes (for the rare big-norm fallback) ----
    u64 r0 = f2add(f2abs(T[0]), f2add(f2abs(T[1]), f2abs(T[2])));
    u64 r1 = f2add(f2abs(T[3]), f2add(f2abs(T[4]), f2abs(T[5])));
    u64 r2 = f2add(f2abs(T[6]), f2add(f2abs(T[7]), f2abs(T[8])));
    float l0, h0, l1, h1, l2, h2;
    upk(l0, h0, r0); upk(l1, h1, r1); upk(l2, h2, r2);
    float a = fmaxf(fmaxf(fmaxf(l0, h0), fmaxf(l1, h1)), fmaxf(l2, h2));

    // s = max(4, e+2) where a in [2^e, 2^{e+1});  a<8 -> s=4 (x <= 0.5)
    int e = ((__float_as_int(a) >> 23) & 0xFF) - 127;
    int s = e + 2;
    if (s < 4) s = 4;
    if (s > 30) s = 30;
    float sc = __int_as_float((127 - s) << 23);  // exact 2^-s
    u64 sc2 = pk(sc, sc);

#pragma unroll
    for (int p = 0; p < 9; p++) T[p] = f2mul(T[p], sc2);

    // ---- degree-8 Paterson-Stockmeyer: E = P0 + T3*(P1 + T3*P2) ----
    // P0 = I + T + T2/2 ; P1 = I/6 + T/24 + T2/120 ; P2 = I/720 + T/5040 + T2/40320
    u64 T2[9], T3[9], M[9], E[9];
    mm3p(T2, T, T);
    mm3p(T3, T2, T);

    const u64 k8 = pk(1.0f / 40320.0f, 1.0f / 40320.0f);
    const u64 k7 = pk(1.0f / 5040.0f,  1.0f / 5040.0f);
    const u64 k6 = pk(1.0f / 720.0f,   1.0f / 720.0f);
    const u64 k5 = pk(1.0f / 120.0f,   1.0f / 120.0f);
    const u64 k4 = pk(1.0f / 24.0f,    1.0f / 24.0f);
    const u64 k3 = pk(1.0f / 6.0f,     1.0f / 6.0f);
    const u64 kh = pk(0.5f, 0.5f);
    const u64 k1 = pk(1.0f, 1.0f);
    const u64 kz = 0ull;

    u64 P2[9];
#pragma unroll
    for (int p = 0; p < 9; p++) {
        u64 d = (p == 0 || p == 4 || p == 8) ? k6 : kz;
        P2[p] = f2fma(T2[p], k8, f2fma(T[p], k7, d));
    }
    mm3p(M, T3, P2);  // M = T3*P2
#pragma unroll
    for (int p = 0; p < 9; p++) {
        u64 d = (p == 0 || p == 4 || p == 8) ? k3 : kz;
        M[p] = f2add(M[p], f2fma(T2[p], k5, f2fma(T[p], k4, d)));  // M += P1
    }
    mm3p(E, T3, M);  // E = T3*(P1 + T3*P2)
#pragma unroll
    for (int p = 0; p < 9; p++) {
        u64 d = (p == 0 || p == 4 || p == 8) ? k1 : kz;
        E[p] = f2add(E[p], f2fma(T2[p], kh, f2add(T[p], d)));  // E += P0
    }

    // ---- squarings: 4 mandatory (uniform), rare extras ----
    u64 Q[9];
#pragma unroll
    for (int i = 0; i < 4; i++) {
        mm3p(Q, E, E);
#pragma unroll
        for (int p = 0; p < 9; p++) E[p] = Q[p];
    }
    for (int i = 4; i < s; i++) {  // essentially never taken
        mm3p(Q, E, E);
#pragma unroll
        for (int p = 0; p < 9; p++) E[p] = Q[p];
    }

    // ---- y = E * x (packed) ----
    u64 y0 = f2fma(E[0], xv0, f2fma(E[1], xv1, f2mul(E[2], xv2)));
    u64 y1 = f2fma(E[3], xv0, f2fma(E[4], xv1, f2mul(E[5], xv2)));
    u64 y2 = f2fma(E[6], xv0, f2fma(E[7], xv1, f2mul(E[8], xv2)));

    float y00, y10, y01, y11, y02, y12;
    upk(y00, y10, y0);  // item0_row0, item1_row0
    upk(y01, y11, y1);
    upk(y02, y12, y2);

    float2* o2 = reinterpret_cast<float2*>(out);
    o2[3 * t + 0] = make_float2(y00, y01);
    o2[3 * t + 1] = make_float2(y02, y10);
    o2[3 * t + 2] = make_float2(y11, y12);
}

extern "C" void kernel_launch(void* const* d_in, const int* in_sizes, int n_in,
                              void* d_out, int out_size) {
    // Identify inputs by element count: psi=54, c=B*6, x=B*3
    const float* c = nullptr;
    const float* x = nullptr;
    const float* psi = nullptr;
    long long maxsz = 0;
    for (int i = 0; i < n_in; i++)
        if ((long long)in_sizes[i] > maxsz) maxsz = in_sizes[i];
    int B = (int)(maxsz / 6);
    for (int i = 0; i < n_in; i++) {
        if (in_sizes[i] == 54) psi = (const float*)d_in[i];
        else if (in_sizes[i] == B * 6) c = (const float*)d_in[i];
        else if (in_sizes[i] == B * 3) x = (const float*)d_in[i];
    }

    float* out = (float*)d_out;
    int nthreads = B / 2;  // 2 items per thread
    int grid = (nthreads + BATCH_THREADS - 1) / BATCH_THREADS;
    transop_expm_kernel<<<grid, BATCH_THREADS>>>(c, x, psi, out, B);
}

// round 3
// speedup vs baseline: 1.1941x; 1.1009x over previous
#include <cuda_runtime.h>

#ifndef BATCH_THREADS
#define BATCH_THREADS 256
#endif

// ---------- packed f32x2 helpers ----------
typedef unsigned long long u64;

__device__ __forceinline__ u64 pk(float lo, float hi) {
    u64 r;
    asm("mov.b64 %0, {%1, %2};" : "=l"(r) : "f"(lo), "f"(hi));
    return r;
}
__device__ __forceinline__ void upk(float& lo, float& hi, u64 v) {
    asm("mov.b64 {%0, %1}, %2;" : "=f"(lo), "=f"(hi) : "l"(v));
}
__device__ __forceinline__ u64 f2fma(u64 a, u64 b, u64 c) {
    u64 d;
    asm("fma.rn.f32x2 %0, %1, %2, %3;" : "=l"(d) : "l"(a), "l"(b), "l"(c));
    return d;
}
__device__ __forceinline__ u64 f2mul(u64 a, u64 b) {
    u64 d;
    asm("mul.rn.f32x2 %0, %1, %2;" : "=l"(d) : "l"(a), "l"(b));
    return d;
}
__device__ __forceinline__ u64 f2add(u64 a, u64 b) {
    u64 d;
    asm("add.rn.f32x2 %0, %1, %2;" : "=l"(d) : "l"(a), "l"(b));
    return d;
}

// packed 3x3 matmul: o = a * b (flat row-major [9], entries are f32x2)
__device__ __forceinline__ void mm3p(u64* __restrict__ o,
                                     const u64* __restrict__ a,
                                     const u64* __restrict__ b) {
#pragma unroll
    for (int i = 0; i < 3; i++) {
#pragma unroll
        for (int j = 0; j < 3; j++) {
            u64 s = f2mul(a[3 * i + 0], b[0 + j]);
            s = f2fma(a[3 * i + 1], b[3 + j], s);
            s = f2fma(a[3 * i + 2], b[6 + j], s);
            o[3 * i + j] = s;
        }
    }
}

__global__ void __launch_bounds__(BATCH_THREADS)
transop_expm_kernel(const float* __restrict__ c,
                    const float* __restrict__ x,
                    const float* __restrict__ psi,
                    float* __restrict__ out,
                    int B) {
    __shared__ u64 sp2[54];
    if (threadIdx.x < 54) {
        float v = psi[threadIdx.x];
        sp2[threadIdx.x] = pk(v, v);
    }
    __syncthreads();

    int t = blockIdx.x * BATCH_THREADS + threadIdx.x;  // items 2t, 2t+1
    if (2 * t >= B) return;

    // ---- c for both items: 12 contiguous floats = 3x float4 ----
    const float4* c4 = reinterpret_cast<const float4*>(c);
    float4 A  = c4[3 * t + 0];
    float4 Bv = c4[3 * t + 1];
    float4 Cv = c4[3 * t + 2];
    u64 cc[6];
    cc[0] = pk(A.x,  Bv.z);
    cc[1] = pk(A.y,  Bv.w);
    cc[2] = pk(A.z,  Cv.x);
    cc[3] = pk(A.w,  Cv.y);
    cc[4] = pk(Bv.x, Cv.z);
    cc[5] = pk(Bv.y, Cv.w);

    // ---- T = sum_m cc[m] * psi[m] (packed, both items) ----
    u64 T[9];
#pragma unroll
    for (int p = 0; p < 9; p++) {
        u64 s = f2mul(cc[0], sp2[p]);
#pragma unroll
        for (int m = 1; m < 6; m++) s = f2fma(cc[m], sp2[m * 9 + p], s);
        T[p] = s;
    }

    // ---- Frobenius norm^2 per lane (9 FFMA2), pick shared s = max lane ----
    u64 fa = f2mul(T[0], T[0]);
#pragma unroll
    for (int p = 1; p < 9; p++) fa = f2fma(T[p], T[p], fa);
    float f0, f1;
    upk(f0, f1, fa);
    float fm = fmaxf(f0, f1);  // max ||T||_F^2 over the two items

    // s = max(3, ceil(0.5*log2(fm) + margin)) so that ||T||_F / 2^s <= 0.9.
    // log2 approx (underestimates by <=0.086): lf = (bits - 127<<23) * 2^-23
    float lf = (float)(__float_as_int(fm) - 0x3f800000) * 1.1920929e-7f;
    int s = __float2int_ru(0.5f * lf + 0.20f);  // 0.152 (log2(1/0.9)) + 0.043 slack
    if (s < 3) s = 3;
    if (s > 12) s = 12;
    float sc = __int_as_float((127 - s) << 23);  // exact 2^-s
    u64 sc2 = pk(sc, sc);
#pragma unroll
    for (int p = 0; p < 9; p++) T[p] = f2mul(T[p], sc2);

    // ---- degree-7 Taylor via Horner in T^2:
    //   E = A0 + T2*(A1 + T2*(A2 + T2*A3)),  Ai = ai*I + bi*T
    //   a: 1, 1/2, 1/24, 1/720   b: 1, 1/6, 1/120, 1/5040
    u64 T2[9];
    mm3p(T2, T, T);

    const u64 kb3 = pk(1.0f / 5040.0f, 1.0f / 5040.0f);
    const u64 ka3 = pk(1.0f / 720.0f,  1.0f / 720.0f);
    const u64 kb2 = pk(1.0f / 120.0f,  1.0f / 120.0f);
    const u64 ka2 = pk(1.0f / 24.0f,   1.0f / 24.0f);
    const u64 kb1 = pk(1.0f / 6.0f,    1.0f / 6.0f);
    const u64 ka1 = pk(0.5f, 0.5f);
    const u64 k1  = pk(1.0f, 1.0f);

    u64 Acc[9];
#pragma unroll
    for (int p = 0; p < 9; p++) Acc[p] = f2mul(T[p], kb3);
    Acc[0] = f2add(Acc[0], ka3);
    Acc[4] = f2add(Acc[4], ka3);
    Acc[8] = f2add(Acc[8], ka3);

    {   // Acc = A2 + T2*Acc
        u64 Tmp[9];
        mm3p(Tmp, T2, Acc);
#pragma unroll
        for (int p = 0; p < 9; p++) Acc[p] = f2fma(T[p], kb2, Tmp[p]);
        Acc[0] = f2add(Acc[0], ka2);
        Acc[4] = f2add(Acc[4], ka2);
        Acc[8] = f2add(Acc[8], ka2);
    }
    {   // Acc = A1 + T2*Acc
        u64 Tmp[9];
        mm3p(Tmp, T2, Acc);
#pragma unroll
        for (int p = 0; p < 9; p++) Acc[p] = f2fma(T[p], kb1, Tmp[p]);
        Acc[0] = f2add(Acc[0], ka1);
        Acc[4] = f2add(Acc[4], ka1);
        Acc[8] = f2add(Acc[8], ka1);
    }
    {   // Acc = A0 + T2*Acc  (A0 = I + T)
        u64 Tmp[9];
        mm3p(Tmp, T2, Acc);
#pragma unroll
        for (int p = 0; p < 9; p++) Acc[p] = f2add(Tmp[p], T[p]);
        Acc[0] = f2add(Acc[0], k1);
        Acc[4] = f2add(Acc[4], k1);
        Acc[8] = f2add(Acc[8], k1);
    }

    // ---- 3 mandatory squarings + rare extras ----
#pragma unroll
    for (int i = 0; i < 3; i++) {
        u64 Q[9];
        mm3p(Q, Acc, Acc);
#pragma unroll
        for (int p = 0; p < 9; p++) Acc[p] = Q[p];
    }
    for (int i = 3; i < s; i++) {  // almost never taken
        u64 Q[9];
        mm3p(Q, Acc, Acc);
#pragma unroll
        for (int p = 0; p < 9; p++) Acc[p] = Q[p];
    }

    // ---- x loads (deferred: shortens live range) ----
    const float2* x2 = reinterpret_cast<const float2*>(x);
    float2 X0 = x2[3 * t + 0];
    float2 X1 = x2[3 * t + 1];
    float2 X2 = x2[3 * t + 2];
    u64 xv0 = pk(X0.x, X1.y);
    u64 xv1 = pk(X0.y, X2.x);
    u64 xv2 = pk(X1.x, X2.y);

    u64 y0 = f2fma(Acc[0], xv0, f2fma(Acc[1], xv1, f2mul(Acc[2], xv2)));
    u64 y1 = f2fma(Acc[3], xv0, f2fma(Acc[4], xv1, f2mul(Acc[5], xv2)));
    u64 y2 = f2fma(Acc[6], xv0, f2fma(Acc[7], xv1, f2mul(Acc[8], xv2)));

    float y00, y10, y01, y11, y02, y12;
    upk(y00, y10, y0);
    upk(y01, y11, y1);
    upk(y02, y12, y2);

    float2* o2 = reinterpret_cast<float2*>(out);
    o2[3 * t + 0] = make_float2(y00, y01);
    o2[3 * t + 1] = make_float2(y02, y10);
    o2[3 * t + 2] = make_float2(y11, y12);
}

extern "C" void kernel_launch(void* const* d_in, const int* in_sizes, int n_in,
                              void* d_out, int out_size) {
    // Identify inputs by element count: psi=54, c=B*6, x=B*3
    const float* c = nullptr;
    const float* x = nullptr;
    const float* psi = nullptr;
    long long maxsz = 0;
    for (int i = 0; i < n_in; i++)
        if ((long long)in_sizes[i] > maxsz) maxsz = in_sizes[i];
    int B = (int)(maxsz / 6);
    for (int i = 0; i < n_in; i++) {
        if (in_sizes[i] == 54) psi = (const float*)d_in[i];
        else if (in_sizes[i] == B * 6) c = (const float*)d_in[i];
        else if (in_sizes[i] == B * 3) x = (const float*)d_in[i];
    }

    float* out = (float*)d_out;
    int nthreads = (B + 1) / 2;  // 2 items per thread
    int grid = (nthreads + BATCH_THREADS - 1) / BATCH_THREADS;
    transop_expm_kernel<<<grid, BATCH_THREADS>>>(c, x, psi, out, B);
}

// round 4
// speedup vs baseline: 1.1997x; 1.0047x over previous
#include <cuda_runtime.h>

#ifndef BATCH_THREADS
#define BATCH_THREADS 256
#endif

// ---------- packed f32x2 helpers ----------
typedef unsigned long long u64;

__device__ __forceinline__ u64 pk(float lo, float hi) {
    u64 r;
    asm("mov.b64 %0, {%1, %2};" : "=l"(r) : "f"(lo), "f"(hi));
    return r;
}
__device__ __forceinline__ void upk(float& lo, float& hi, u64 v) {
    asm("mov.b64 {%0, %1}, %2;" : "=f"(lo), "=f"(hi) : "l"(v));
}
__device__ __forceinline__ u64 f2fma(u64 a, u64 b, u64 c) {
    u64 d;
    asm("fma.rn.f32x2 %0, %1, %2, %3;" : "=l"(d) : "l"(a), "l"(b), "l"(c));
    return d;
}
__device__ __forceinline__ u64 f2mul(u64 a, u64 b) {
    u64 d;
    asm("mul.rn.f32x2 %0, %1, %2;" : "=l"(d) : "l"(a), "l"(b));
    return d;
}
__device__ __forceinline__ u64 f2add(u64 a, u64 b) {
    u64 d;
    asm("add.rn.f32x2 %0, %1, %2;" : "=l"(d) : "l"(a), "l"(b));
    return d;
}

// packed 3x3 matmul: o = a * b (flat row-major [9], entries are f32x2)
__device__ __forceinline__ void mm3p(u64* __restrict__ o,
                                     const u64* __restrict__ a,
                                     const u64* __restrict__ b) {
#pragma unroll
    for (int i = 0; i < 3; i++) {
#pragma unroll
        for (int j = 0; j < 3; j++) {
            u64 s = f2mul(a[3 * i + 0], b[0 + j]);
            s = f2fma(a[3 * i + 1], b[3 + j], s);
            s = f2fma(a[3 * i + 2], b[6 + j], s);
            o[3 * i + j] = s;
        }
    }
}

__global__ void __launch_bounds__(BATCH_THREADS, 5)
transop_expm_kernel(const float* __restrict__ c,
                    const float* __restrict__ x,
                    const float* __restrict__ psi,
                    float* __restrict__ out,
                    int B) {
    __shared__ u64 sp2[54];
    if (threadIdx.x < 54) {
        float v = psi[threadIdx.x];
        sp2[threadIdx.x] = pk(v, v);
    }
    __syncthreads();

    int t = blockIdx.x * BATCH_THREADS + threadIdx.x;  // items 2t, 2t+1
    if (2 * t >= B) return;

    // ---- c for both items: 12 contiguous floats = 3x float4 ----
    const float4* c4 = reinterpret_cast<const float4*>(c);
    float4 A  = c4[3 * t + 0];
    float4 Bv = c4[3 * t + 1];
    float4 Cv = c4[3 * t + 2];
    u64 cc[6];
    cc[0] = pk(A.x,  Bv.z);
    cc[1] = pk(A.y,  Bv.w);
    cc[2] = pk(A.z,  Cv.x);
    cc[3] = pk(A.w,  Cv.y);
    cc[4] = pk(Bv.x, Cv.z);
    cc[5] = pk(Bv.y, Cv.w);

    // ---- T = sum_m cc[m] * psi[m] (packed, both items) ----
    u64 T[9];
#pragma unroll
    for (int p = 0; p < 9; p++) {
        u64 s = f2mul(cc[0], sp2[p]);
#pragma unroll
        for (int m = 1; m < 6; m++) s = f2fma(cc[m], sp2[m * 9 + p], s);
        T[p] = s;
    }

    // ---- Frobenius norm^2 per lane; shared s = max over the two items ----
    u64 fa = f2mul(T[0], T[0]);
#pragma unroll
    for (int p = 1; p < 9; p++) fa = f2fma(T[p], T[p], fa);
    float f0, f1;
    upk(f0, f1, fa);
    float fm = fmaxf(f0, f1);

    // Want ||T||_F / 2^s <= 0.45  ->  s >= 0.5*log2(fm) + 1.152.
    // lf underestimates log2(fm) by <= 0.086 -> add 0.043+slack.
    float lf = (float)(__float_as_int(fm) - 0x3f800000) * 1.1920929e-7f;
    int s = __float2int_ru(0.5f * lf + 1.21f);
    if (s < 3) s = 3;
    if (s > 12) s = 12;
    float sc = __int_as_float((127 - s) << 23);  // exact 2^-s
    u64 sc2 = pk(sc, sc);
#pragma unroll
    for (int p = 0; p < 9; p++) T[p] = f2mul(T[p], sc2);

    // ---- degree-5 Taylor via 2-stage Horner in T^2:
    //   E = A0 + T2*(A1 + T2*A2)
    //   A2 = I/24 + T/120 ; A1 = I/2 + T/6 ; A0 = I + T
    u64 T2[9];
    mm3p(T2, T, T);

    const u64 kb2 = pk(1.0f / 120.0f, 1.0f / 120.0f);
    const u64 ka2 = pk(1.0f / 24.0f,  1.0f / 24.0f);
    const u64 kb1 = pk(1.0f / 6.0f,   1.0f / 6.0f);
    const u64 ka1 = pk(0.5f, 0.5f);
    const u64 k1  = pk(1.0f, 1.0f);

    u64 Acc[9];
#pragma unroll
    for (int p = 0; p < 9; p++) Acc[p] = f2mul(T[p], kb2);
    Acc[0] = f2add(Acc[0], ka2);
    Acc[4] = f2add(Acc[4], ka2);
    Acc[8] = f2add(Acc[8], ka2);

    {   // Acc = A1 + T2*Acc
        u64 Tmp[9];
        mm3p(Tmp, T2, Acc);
#pragma unroll
        for (int p = 0; p < 9; p++) Acc[p] = f2fma(T[p], kb1, Tmp[p]);
        Acc[0] = f2add(Acc[0], ka1);
        Acc[4] = f2add(Acc[4], ka1);
        Acc[8] = f2add(Acc[8], ka1);
    }
    {   // Acc = A0 + T2*Acc  (A0 = I + T)
        u64 Tmp[9];
        mm3p(Tmp, T2, Acc);
#pragma unroll
        for (int p = 0; p < 9; p++) Acc[p] = f2add(Tmp[p], T[p]);
        Acc[0] = f2add(Acc[0], k1);
        Acc[4] = f2add(Acc[4], k1);
        Acc[8] = f2add(Acc[8], k1);
    }

    // ---- 3 mandatory squarings (typical case, fully unrolled) ----
#pragma unroll
    for (int i = 0; i < 3; i++) {
        u64 Q[9];
        mm3p(Q, Acc, Acc);
#pragma unroll
        for (int p = 0; p < 9; p++) Acc[p] = Q[p];
    }
    // rare tail squarings (||T||_F > 3.6)
    for (int i = 3; i < s; i++) {
        u64 Q[9];
        mm3p(Q, Acc, Acc);
#pragma unroll
        for (int p = 0; p < 9; p++) Acc[p] = Q[p];
    }

    // ---- x loads (deferred) ----
    const float2* x2 = reinterpret_cast<const float2*>(x);
    float2 X0 = x2[3 * t + 0];
    float2 X1 = x2[3 * t + 1];
    float2 X2 = x2[3 * t + 2];
    u64 xv0 = pk(X0.x, X1.y);
    u64 xv1 = pk(X0.y, X2.x);
    u64 xv2 = pk(X1.x, X2.y);

    u64 y0 = f2fma(Acc[0], xv0, f2fma(Acc[1], xv1, f2mul(Acc[2], xv2)));
    u64 y1 = f2fma(Acc[3], xv0, f2fma(Acc[4], xv1, f2mul(Acc[5], xv2)));
    u64 y2 = f2fma(Acc[6], xv0, f2fma(Acc[7], xv1, f2mul(Acc[8], xv2)));

    float y00, y10, y01, y11, y02, y12;
    upk(y00, y10, y0);
    upk(y01, y11, y1);
    upk(y02, y12, y2);

    float2* o2 = reinterpret_cast<float2*>(out);
    o2[3 * t + 0] = make_float2(y00, y01);
    o2[3 * t + 1] = make_float2(y02, y10);
    o2[3 * t + 2] = make_float2(y11, y12);
}

extern "C" void kernel_launch(void* const* d_in, const int* in_sizes, int n_in,
                              void* d_out, int out_size) {
    // Identify inputs by element count: psi=54, c=B*6, x=B*3
    const float* c = nullptr;
    const float* x = nullptr;
    const float* psi = nullptr;
    long long maxsz = 0;
    for (int i = 0; i < n_in; i++)
        if ((long long)in_sizes[i] > maxsz) maxsz = in_sizes[i];
    int B = (int)(maxsz / 6);
    for (int i = 0; i < n_in; i++) {
        if (in_sizes[i] == 54) psi = (const float*)d_in[i];
        else if (in_sizes[i] == B * 6) c = (const float*)d_in[i];
        else if (in_sizes[i] == B * 3) x = (const float*)d_in[i];
    }

    float* out = (float*)d_out;
    int nthreads = (B + 1) / 2;  // 2 items per thread
    int grid = (nthreads + BATCH_THREADS - 1) / BATCH_THREADS;
    transop_expm_kernel<<<grid, BATCH_THREADS>>>(c, x, psi, out, B);
}